// round 8
// baseline (speedup 1.0000x reference)
#include <cuda_runtime.h>
#include <cstdint>

// B=2, C=128, IC=64, W=H=32, Z=128, nz=64. 2048 tiles of x[C=128][Z=128].
// Warp-level tf32 mma.sync m16n8k8 (base sm_103 target; tcgen05 is 'a'-gated).
//   GEMM1 D1[o=128][z=128] = Wgp[o][Ci] @ x[Ci][z]   (g rows 0..63, phi 64..127)
//   epi1 (register): pool z-pairs; g -> gp[j][c]/64, phi -> bb[j]; a[z]=vt.x scalar
//   GEMM2 D2[z][c=64] = f @ gp, f = relu(a+bb)
//   GEMM3 D3[z][Co=128] = y @ Ww^T ; out = D3*alpha + beta + x
// R8: GEMM1 warp grid 2Mx4N (halves B LDS), A+B double-buffered; phi warps own a
// full z-quarter -> bb written directly (one fewer barrier).

#define N_TILES 2048
#define THREADS 256

__device__ __forceinline__ float to_tf32(float v) {
    uint32_t u; asm("cvt.rna.tf32.f32 %0, %1;" : "=r"(u) : "f"(v));
    return __uint_as_float(u);
}
__device__ __forceinline__ void mma8(float* d, uint32_t a0, uint32_t a1, uint32_t a2,
                                     uint32_t a3, uint32_t b0, uint32_t b1) {
    asm volatile("mma.sync.aligned.m16n8k8.row.col.f32.tf32.tf32.f32 "
                 "{%0,%1,%2,%3}, {%4,%5,%6,%7}, {%8,%9}, {%0,%1,%2,%3};"
                 : "+f"(d[0]), "+f"(d[1]), "+f"(d[2]), "+f"(d[3])
                 : "r"(a0), "r"(a1), "r"(a2), "r"(a3), "r"(b0), "r"(b1));
}

// ---- precomputed globals ----
__device__ float d_vt[128];      // cat_w[:64]^T @ theta_w (theta conv collapsed)
__device__ float d_ct;
__device__ float d_alpha[128];
__device__ float d_beta[128];
__device__ float d_A1f[16384];   // Wgp frags: [strip8][ks16][lane32][r4] (tf32)
__device__ float d_WwB[8192];    // Ww  frags: [ks8][nt16][lane32][r2]    (tf32)

__global__ void setup_kernel(const float* __restrict__ theta_w,
                             const float* __restrict__ theta_b,
                             const float* __restrict__ cat_w,
                             const float* __restrict__ W_b,
                             const float* __restrict__ bn_g,
                             const float* __restrict__ bn_b,
                             const float* __restrict__ bn_m,
                             const float* __restrict__ bn_v,
                             const float* __restrict__ g_w,
                             const float* __restrict__ phi_w,
                             const float* __restrict__ W_w)
{
    int tid = threadIdx.x;  // 256
    if (tid < 128) {
        float s = 0.f;
        for (int ic = 0; ic < 64; ic++) s += cat_w[ic] * theta_w[ic * 128 + tid];
        d_vt[tid] = s;
        float a = bn_g[tid] * rsqrtf(bn_v[tid] + 1e-5f);
        d_alpha[tid] = a;
        d_beta[tid]  = (W_b[tid] - bn_m[tid]) * a + bn_b[tid];
    }
    if (tid == 0) {
        float s = 0.f;
        for (int ic = 0; ic < 64; ic++) s += cat_w[ic] * theta_b[ic];
        d_ct = s;
    }
    // A frags GEMM1: a0:(row,col) a1:(row+8,col) a2:(row,col+4) a3:(row+8,col+4)
    for (int idx = tid; idx < 16384; idx += 256) {
        int r = idx & 3, lane = (idx >> 2) & 31, ks = (idx >> 7) & 15, s = idx >> 11;
        int o  = s * 16 + (lane >> 2) + (r & 1) * 8;
        int Ci = ks * 8 + (lane & 3) + ((r >> 1) & 1) * 4;
        float v = (o < 64) ? g_w[o * 128 + Ci] : phi_w[(o - 64) * 128 + Ci];
        d_A1f[idx] = to_tf32(v);
    }
    // B frags GEMM3: b0:(k,n) b1:(k+4,n); k=c, n=Co
    for (int idx = tid; idx < 8192; idx += 256) {
        int r = idx & 1, lane = (idx >> 1) & 31, nt = (idx >> 6) & 15, ks = idx >> 10;
        int c  = ks * 8 + (lane & 3) + r * 4;
        int Co = nt * 8 + (lane >> 2);
        d_WwB[idx] = to_tf32(W_w[Co * 64 + c]);
    }
}

// ---- smem layout (floats). x region overlaid by f/gp/y after GEMM1. ----
#define OFF_X    0        // x [Ci=128][136]  (136%32==8, frag reads conflict-free)
#define OFF_F    0        // f/y [z=128][68]  (68%32==4)        -- overlay
#define OFF_GP   8704     // gp [j=64][72]    (72%32==8)        -- overlay
#define OFF_AS   17408    // a[z] 128
#define OFF_BB   17536    // bb[j] 64
#define OFF_GB   17600
#define OFF_PB   17664
#define OFF_WP   17728
#define OFF_AL   17792
#define OFF_BE   17920
#define OFF_VT   18048
#define SMEM_FLOATS 18176
#define SMEM_BYTES (SMEM_FLOATS * 4)   // 72704 -> 2 CTAs/SM

__global__ void __launch_bounds__(THREADS, 2)
nonlocal_kernel(const float* __restrict__ x,
                const float* __restrict__ g_b,
                const float* __restrict__ phi_b,
                const float* __restrict__ cat_w,
                float* __restrict__ out)
{
    extern __shared__ float sm[];
    const int tid  = threadIdx.x;
    const int lane = tid & 31;
    const int wid  = tid >> 5;     // 0..7
    const int q    = lane & 3;
    const int l4   = lane >> 2;

    const int n  = blockIdx.x;
    const int b  = n >> 10;
    const int wh = n & 1023;
    const size_t gbase = (size_t)b * 16777216 + (size_t)wh * 128;  // + Ci*131072 + z
    const float* xg = x + gbase;

    // ---- stage A: load x tile + small vectors ----
    {
        const float4* xg4 = (const float4*)xg;
        #pragma unroll
        for (int it = 0; it < 16; it++) {
            int idx = it * 256 + tid;            // 4096 float4
            int Ci = idx >> 5, z4 = idx & 31;
            *(float4*)(sm + OFF_X + Ci * 136 + z4 * 4) = xg4[(size_t)Ci * 32768 + z4];
        }
    }
    if (tid < 128) { sm[OFF_VT + tid] = d_vt[tid]; sm[OFF_AL + tid] = d_alpha[tid]; sm[OFF_BE + tid] = d_beta[tid]; }
    if (tid < 64)  { sm[OFF_GB + tid] = g_b[tid]; sm[OFF_PB + tid] = phi_b[tid]; sm[OFF_WP + tid] = cat_w[64 + tid]; }
    __syncthreads();

    // ---- a[z] = ct + vt . x[:,z]  (scalar; theta conv collapsed) ----
    if (tid < 128) {
        float s = d_ct;
        #pragma unroll 8
        for (int Ci = 0; Ci < 128; Ci++)
            s = fmaf(sm[OFF_VT + Ci], sm[OFF_X + Ci * 136 + tid], s);
        sm[OFF_AS + tid] = s;
    }

    // ---- GEMM1: warp grid 2 M-halves(64 o) x 4 z-quarters(32 z) ----
    const int mh = wid & 1;        // o half: o = mh*64 .. +63 (4 frag strips)
    const int nq = wid >> 1;       // z quarter: z = nq*32 .. +31 (4 nt)
    const int zb = nq * 32;

    float d1[4][4][4];
    #pragma unroll
    for (int mt = 0; mt < 4; mt++)
        #pragma unroll
        for (int nt = 0; nt < 4; nt++)
            #pragma unroll
            for (int r = 0; r < 4; r++) d1[mt][nt][r] = 0.f;

    {
        const float4* gA = ((const float4*)d_A1f) + (mh * 4) * 512;  // 4 strips
        float4 a_cur[4], a_nxt[4];
        float  b_cur[4][2], b_nxt[4][2];
        #pragma unroll
        for (int mt = 0; mt < 4; mt++) a_cur[mt] = gA[mt * 512 + lane];
        #pragma unroll
        for (int nt = 0; nt < 4; nt++) {
            const float* xr = sm + OFF_X + q * 136 + zb + 8 * nt + l4;
            b_cur[nt][0] = xr[0];
            b_cur[nt][1] = xr[4 * 136];
        }
        #pragma unroll 1
        for (int ks = 0; ks < 16; ks++) {
            if (ks < 15) {
                #pragma unroll
                for (int mt = 0; mt < 4; mt++)
                    a_nxt[mt] = gA[mt * 512 + (ks + 1) * 32 + lane];
                #pragma unroll
                for (int nt = 0; nt < 4; nt++) {
                    const float* xr = sm + OFF_X + (8 * (ks + 1) + q) * 136 + zb + 8 * nt + l4;
                    b_nxt[nt][0] = xr[0];
                    b_nxt[nt][1] = xr[4 * 136];
                }
            }
            #pragma unroll
            for (int mt = 0; mt < 4; mt++) {
                uint32_t a0 = __float_as_uint(a_cur[mt].x);
                uint32_t a1 = __float_as_uint(a_cur[mt].y);
                uint32_t a2 = __float_as_uint(a_cur[mt].z);
                uint32_t a3 = __float_as_uint(a_cur[mt].w);
                #pragma unroll
                for (int nt = 0; nt < 4; nt++)
                    mma8(d1[mt][nt], a0, a1, a2, a3,
                         __float_as_uint(b_cur[nt][0]), __float_as_uint(b_cur[nt][1]));
            }
            #pragma unroll
            for (int mt = 0; mt < 4; mt++) a_cur[mt] = a_nxt[mt];
            #pragma unroll
            for (int nt = 0; nt < 4; nt++) {
                b_cur[nt][0] = b_nxt[nt][0];
                b_cur[nt][1] = b_nxt[nt][1];
            }
        }
    }
    __syncthreads();   // all GEMM1/a reads of x done -> overlay region writable

    // ---- epi1: pool z-pairs in-register ----
    if (mh == 0) {     // g half: full gp columns for this z-quarter
        #pragma unroll
        for (int mt = 0; mt < 4; mt++) {
            const int o0 = mt * 16 + l4, o1 = o0 + 8;
            const float gb0 = sm[OFF_GB + o0], gb1 = sm[OFF_GB + o1];
            #pragma unroll
            for (int nt = 0; nt < 4; nt++) {
                int j = nq * 16 + nt * 4 + q;
                sm[OFF_GP + j * 72 + o0] = (fmaxf(d1[mt][nt][0], d1[mt][nt][1]) + gb0) * 0.015625f;
                sm[OFF_GP + j * 72 + o1] = (fmaxf(d1[mt][nt][2], d1[mt][nt][3]) + gb1) * 0.015625f;
            }
        }
    } else {           // phi half: this warp owns ALL 64 phi channels -> bb direct
        #pragma unroll
        for (int nt = 0; nt < 4; nt++) {
            float v = 0.f;
            #pragma unroll
            for (int mt = 0; mt < 4; mt++) {
                const int p0 = mt * 16 + l4, p1 = p0 + 8;
                v += sm[OFF_WP + p0] * (fmaxf(d1[mt][nt][0], d1[mt][nt][1]) + sm[OFF_PB + p0])
                   + sm[OFF_WP + p1] * (fmaxf(d1[mt][nt][2], d1[mt][nt][3]) + sm[OFF_PB + p1]);
            }
            v += __shfl_xor_sync(0xFFFFFFFFu, v, 16);
            v += __shfl_xor_sync(0xFFFFFFFFu, v, 8);
            v += __shfl_xor_sync(0xFFFFFFFFu, v, 4);
            if (l4 == 0) sm[OFF_BB + nq * 16 + nt * 4 + q] = v;
        }
    }
    __syncthreads();
    {   // f[z][j] = relu(a[z] + bb[j])
        const int z = tid >> 1, half = tid & 1;
        const float az = sm[OFF_AS + z];
        #pragma unroll
        for (int jj = 0; jj < 8; jj++) {
            int j = half * 32 + 4 * jj;
            float4 v;
            v.x = fmaxf(az + sm[OFF_BB + j + 0], 0.f);
            v.y = fmaxf(az + sm[OFF_BB + j + 1], 0.f);
            v.z = fmaxf(az + sm[OFF_BB + j + 2], 0.f);
            v.w = fmaxf(az + sm[OFF_BB + j + 3], 0.f);
            *(float4*)(sm + OFF_F + z * 68 + j) = v;
        }
    }
    __syncthreads();

    // ---- GEMM2: D2[z][c] = f @ gp, warp = z-strip 16 (wid) ----
    float d2[8][4];
    #pragma unroll
    for (int nt = 0; nt < 8; nt++)
        #pragma unroll
        for (int r = 0; r < 4; r++) d2[nt][r] = 0.f;

    #pragma unroll 1
    for (int ks = 0; ks < 8; ks++) {
        const float* fr = sm + OFF_F + (16 * wid + l4) * 68 + 8 * ks + q;
        uint32_t a0 = __float_as_uint(fr[0]);
        uint32_t a1 = __float_as_uint(fr[8 * 68]);
        uint32_t a2 = __float_as_uint(fr[4]);
        uint32_t a3 = __float_as_uint(fr[8 * 68 + 4]);
        const float* gr0 = sm + OFF_GP + (8 * ks + q) * 72 + l4;
        const float* gr1 = gr0 + 4 * 72;
        #pragma unroll
        for (int nt = 0; nt < 8; nt++) {
            uint32_t b0 = __float_as_uint(gr0[8 * nt]);
            uint32_t b1 = __float_as_uint(gr1[8 * nt]);
            mma8(d2[nt], a0, a1, a2, a3, b0, b1);
        }
    }
    // epi2: y overwrites own f strip
    #pragma unroll
    for (int nt = 0; nt < 8; nt++) {
        int c = 8 * nt + 2 * q;
        *(float2*)(sm + OFF_F + (16 * wid + l4) * 68 + c)     = make_float2(d2[nt][0], d2[nt][1]);
        *(float2*)(sm + OFF_F + (16 * wid + l4 + 8) * 68 + c) = make_float2(d2[nt][2], d2[nt][3]);
    }
    __syncthreads();   // y read cross-warp in GEMM3

    // ---- GEMM3: warp grid 4 z-strips(32) x 2 Co-halves(64) ----
    {
        const int zq3 = wid >> 1, ch = wid & 1;
        const int zb3 = zq3 * 32, cob = ch * 64;

        float d3[2][8][4];
        #pragma unroll
        for (int mt = 0; mt < 2; mt++)
            #pragma unroll
            for (int nt = 0; nt < 8; nt++)
                #pragma unroll
                for (int r = 0; r < 4; r++) d3[mt][nt][r] = 0.f;

        const float2* gB = (const float2*)d_WwB;
        #pragma unroll 1
        for (int ks = 0; ks < 8; ks++) {
            const float* yr0 = sm + OFF_F + (zb3 + l4) * 68 + 8 * ks + q;
            const float* yr1 = yr0 + 16 * 68;
            uint32_t a00 = __float_as_uint(yr0[0]);
            uint32_t a01 = __float_as_uint(yr0[8 * 68]);
            uint32_t a02 = __float_as_uint(yr0[4]);
            uint32_t a03 = __float_as_uint(yr0[8 * 68 + 4]);
            uint32_t a10 = __float_as_uint(yr1[0]);
            uint32_t a11 = __float_as_uint(yr1[8 * 68]);
            uint32_t a12 = __float_as_uint(yr1[4]);
            uint32_t a13 = __float_as_uint(yr1[8 * 68 + 4]);
            #pragma unroll
            for (int nt = 0; nt < 8; nt++) {
                float2 bw = gB[(ks * 16 + ch * 8 + nt) * 32 + lane];
                uint32_t b0 = __float_as_uint(bw.x), b1 = __float_as_uint(bw.y);
                mma8(d3[0][nt], a00, a01, a02, a03, b0, b1);
                mma8(d3[1][nt], a10, a11, a12, a13, b0, b1);
            }
        }

        // ---- epi3: out = D3*alpha + beta + x (residual from global/L2) ----
        #pragma unroll
        for (int mt = 0; mt < 2; mt++) {
            const int z0 = zb3 + 16 * mt + l4, z1 = z0 + 8;
            #pragma unroll
            for (int nt = 0; nt < 8; nt++) {
                int Co0 = cob + 8 * nt + 2 * q, Co1 = Co0 + 1;
                float al0 = sm[OFF_AL + Co0], be0 = sm[OFF_BE + Co0];
                float al1 = sm[OFF_AL + Co1], be1 = sm[OFF_BE + Co1];
                size_t p00 = gbase + (size_t)Co0 * 131072 + z0;
                size_t p10 = gbase + (size_t)Co1 * 131072 + z0;
                size_t p01 = gbase + (size_t)Co0 * 131072 + z1;
                size_t p11 = gbase + (size_t)Co1 * 131072 + z1;
                out[p00] = fmaf(d3[mt][nt][0], al0, be0) + __ldg(x + p00);
                out[p10] = fmaf(d3[mt][nt][1], al1, be1) + __ldg(x + p10);
                out[p01] = fmaf(d3[mt][nt][2], al0, be0) + __ldg(x + p01);
                out[p11] = fmaf(d3[mt][nt][3], al1, be1) + __ldg(x + p11);
            }
        }
    }
}

extern "C" void kernel_launch(void* const* d_in, const int* in_sizes, int n_in,
                              void* d_out, int out_size)
{
    const float* x       = (const float*)d_in[0];
    const float* g_w     = (const float*)d_in[1];
    const float* g_b     = (const float*)d_in[2];
    const float* theta_w = (const float*)d_in[3];
    const float* theta_b = (const float*)d_in[4];
    const float* phi_w   = (const float*)d_in[5];
    const float* phi_b   = (const float*)d_in[6];
    const float* cat_w   = (const float*)d_in[7];
    const float* W_w     = (const float*)d_in[8];
    const float* W_b     = (const float*)d_in[9];
    const float* bn_g    = (const float*)d_in[10];
    const float* bn_b    = (const float*)d_in[11];
    const float* bn_m    = (const float*)d_in[12];
    const float* bn_v    = (const float*)d_in[13];

    cudaFuncSetAttribute(nonlocal_kernel,
                         cudaFuncAttributeMaxDynamicSharedMemorySize, SMEM_BYTES);

    setup_kernel<<<1, 256>>>(theta_w, theta_b, cat_w, W_b,
                             bn_g, bn_b, bn_m, bn_v, g_w, phi_w, W_w);
    nonlocal_kernel<<<N_TILES, THREADS, SMEM_BYTES>>>(x, g_b, phi_b, cat_w,
                                                      (float*)d_out);
}